// round 7
// baseline (speedup 1.0000x reference)
#include <cuda_runtime.h>
#include <cstdint>

#define BATCH  512
#define LATENT 256
#define HID    1024
#define OUTD   128
#define SEQ    96
#define GATES  4096   // 4*HID
#define EPS    1e-5f

// ---------------------------------------------------------------------------
// Persistent device scratch (static __device__ arrays — no runtime alloc).
// ---------------------------------------------------------------------------
__device__ float g_tmp[BATCH * 2048];       // init-GEMM tmp (512x2048)
__device__ float g_h1a[BATCH * HID];
__device__ float g_h1b[BATCH * HID];
__device__ float g_c1[BATCH * HID];
__device__ float g_h2a[BATCH * HID];
__device__ float g_h2b[BATCH * HID];
__device__ float g_c2[BATCH * HID];
__device__ float g_x[BATCH * OUTD];         // step input (y of previous step)
__device__ float g_p1[BATCH * HID];         // p1 GEMM output (pre-LN)
__device__ float g_part[4 * BATCH * OUTD];  // p2 split-K partials

// ---------------------------------------------------------------------------
// Helpers
// ---------------------------------------------------------------------------
__device__ __forceinline__ uint32_t f2tf32(float f) {
    uint32_t r;
    asm("cvt.rna.tf32.f32 %0, %1;" : "=r"(r) : "f"(f));
    return r;
}

__device__ __forceinline__ void mma_tf32(float* d, const uint32_t* a, const uint32_t* b) {
    asm volatile(
        "mma.sync.aligned.m16n8k8.row.col.f32.tf32.tf32.f32 "
        "{%0,%1,%2,%3}, {%4,%5,%6,%7}, {%8,%9}, {%0,%1,%2,%3};"
        : "+f"(d[0]), "+f"(d[1]), "+f"(d[2]), "+f"(d[3])
        : "r"(a[0]), "r"(a[1]), "r"(a[2]), "r"(a[3]),
          "r"(b[0]), "r"(b[1]));
}

__device__ __forceinline__ float gelu_exact(float x) {
    return 0.5f * x * (1.0f + erff(x * 0.70710678118654752f));
}
__device__ __forceinline__ float sigmoidf_(float x) {
    return 1.0f / (1.0f + expf(-x));
}

// block-wide sum of two values (blockDim.x == 256)
__device__ __forceinline__ void block_reduce2(float& a, float& b) {
    __shared__ float sa[8], sb[8];
    #pragma unroll
    for (int o = 16; o; o >>= 1) {
        a += __shfl_xor_sync(0xffffffffu, a, o);
        b += __shfl_xor_sync(0xffffffffu, b, o);
    }
    int w = threadIdx.x >> 5, l = threadIdx.x & 31;
    if (l == 0) { sa[w] = a; sb[w] = b; }
    __syncthreads();
    if (threadIdx.x < 32) {
        float ta = (l < 8) ? sa[l] : 0.0f;
        float tb = (l < 8) ? sb[l] : 0.0f;
        #pragma unroll
        for (int o = 4; o; o >>= 1) {
            ta += __shfl_xor_sync(0xffffffffu, ta, o);
            tb += __shfl_xor_sync(0xffffffffu, tb, o);
        }
        if (l == 0) { sa[0] = ta; sb[0] = tb; }
    }
    __syncthreads();
    a = sa[0];
    b = sb[0];
}

// ---------------------------------------------------------------------------
// 512-thread tf32 GEMM (16 warps, 32x32 warp tiles), dual input, optional
// fused LSTM epilogue. BM=BN=128 fixed.
//   result = A1[M,K1] @ W1^T (+ A2[M,K2] @ W2^T) + bias
// LSTM mode: block bx covers columns j0=bx*32 of ALL FOUR gates
// (W rows {j, HID+j, 2HID+j, 3HID+j}); epilogue computes c/h in-kernel.
// 4-stage cp.async ring, issue distance 2, ONE __syncthreads per K-iter.
// Dynamic smem: 4*256*36*4 = 147456 B.
// ---------------------------------------------------------------------------
template<bool LSTM>
__global__ __launch_bounds__(512, 1)
void gemm512(const float* __restrict__ A1, const float* __restrict__ W1, int K1,
             const float* __restrict__ A2, const float* __restrict__ W2, int K2,
             const float* __restrict__ bias,
             float* __restrict__ C, int N,
             float* __restrict__ c_st, float* __restrict__ h_new)
{
    constexpr int MT = 2;              // 32 rows  = 2 x m16
    constexpr int NT = 4;              // 32 cols  = 4 x n8
    constexpr int BUFW = 256 * 36;     // floats per ring buffer (A 128 + W 128 rows)

    extern __shared__ __align__(16) float sm[];

    const int tid  = threadIdx.x;
    const int lane = tid & 31;
    const int wid  = tid >> 5;            // 0..15
    const int wm   = (wid >> 2) * 32;     // warp row offset (4 row-groups)
    const int wn   = (wid & 3) * 32;      // warp col offset (4 col-groups)
    const int grp  = lane >> 2;
    const int tig  = lane & 3;
    const int rowBase = blockIdx.y * 128;
    const int colBase = blockIdx.x * (LSTM ? 32 : 128);  // j0 in LSTM mode

    const int n1 = K1 >> 5;
    const int n2 = K2 >> 5;
    const int tot = n1 + n2;

    float acc[MT][NT][4];
    #pragma unroll
    for (int i = 0; i < MT; i++)
        #pragma unroll
        for (int j = 0; j < NT; j++)
            #pragma unroll
            for (int k = 0; k < 4; k++)
                acc[i][j][k] = 0.0f;

    auto issue = [&](int it, int b) {
        const float* A; const float* W; int K; int k0;
        if (it < n1) { A = A1; W = W1; K = K1; k0 = it << 5; }
        else         { A = A2; W = W2; K = K2; k0 = (it - n1) << 5; }
        // A tile: 128 rows x 8 float4 chunks = 1024 chunks, 2 per thread
        #pragma unroll
        for (int i = 0; i < 2; i++) {
            int chunk = tid + i * 512;
            int r = chunk >> 3, c16 = chunk & 7;
            const float* g = A + (size_t)(rowBase + r) * K + k0 + c16 * 4;
            uint32_t s = (uint32_t)__cvta_generic_to_shared(&sm[b * BUFW + r * 36 + c16 * 4]);
            asm volatile("cp.async.cg.shared.global [%0], [%1], 16;\n" :: "r"(s), "l"(g));
        }
        // W tile: 128 rows x 8 chunks
        #pragma unroll
        for (int i = 0; i < 2; i++) {
            int chunk = tid + i * 512;
            int r = chunk >> 3, c16 = chunk & 7;
            int wrow = LSTM ? ((r >> 5) * HID + colBase + (r & 31)) : (colBase + r);
            const float* g = W + (size_t)wrow * K + k0 + c16 * 4;
            uint32_t s = (uint32_t)__cvta_generic_to_shared(&sm[b * BUFW + 128 * 36 + r * 36 + c16 * 4]);
            asm volatile("cp.async.cg.shared.global [%0], [%1], 16;\n" :: "r"(s), "l"(g));
        }
    };

    auto compute = [&](int b) {
        const float* Asb = &sm[b * BUFW];
        const float* Wsb = &sm[b * BUFW + 128 * 36];
        #pragma unroll
        for (int kk = 0; kk < 32; kk += 8) {
            uint32_t af[MT][4];
            #pragma unroll
            for (int mt = 0; mt < MT; mt++) {
                int r = wm + mt * 16 + grp;
                af[mt][0] = f2tf32(Asb[r * 36 + kk + tig]);
                af[mt][1] = f2tf32(Asb[(r + 8) * 36 + kk + tig]);
                af[mt][2] = f2tf32(Asb[r * 36 + kk + tig + 4]);
                af[mt][3] = f2tf32(Asb[(r + 8) * 36 + kk + tig + 4]);
            }
            uint32_t bf[NT][2];
            #pragma unroll
            for (int nt = 0; nt < NT; nt++) {
                int n = wn + nt * 8 + grp;
                bf[nt][0] = f2tf32(Wsb[n * 36 + kk + tig]);
                bf[nt][1] = f2tf32(Wsb[n * 36 + kk + tig + 4]);
            }
            #pragma unroll
            for (int mt = 0; mt < MT; mt++)
                #pragma unroll
                for (int nt = 0; nt < NT; nt++)
                    mma_tf32(acc[mt][nt], af[mt], bf[nt]);
        }
    };

    // 4-stage ring, issue distance 2: prologue issues groups 0,1.
    issue(0, 0);
    asm volatile("cp.async.commit_group;");
    if (tot > 1) {
        issue(1, 1);
        asm volatile("cp.async.commit_group;");
    }
    for (int it = 0; it < tot; it++) {
        if (it + 2 < tot) {
            issue(it + 2, (it + 2) & 3);   // buffer last consumed by compute(it-2)
            asm volatile("cp.async.commit_group;");
        }
        int pend = tot - 1 - it;           // committed groups newer than 'it'
        if (pend >= 2)      asm volatile("cp.async.wait_group 2;");
        else if (pend == 1) asm volatile("cp.async.wait_group 1;");
        else                asm volatile("cp.async.wait_group 0;");
        __syncthreads();                   // single barrier per K-iteration
        compute(it & 3);
    }

    if constexpr (LSTM) {
        __syncthreads();   // all warps done with ring buffers before smem reuse
        // Stage the four 128x32 gate tiles in smem (stride 33, 67.6 KB).
        float* sg = sm;
        #pragma unroll
        for (int mt = 0; mt < MT; mt++) {
            int r = wm + mt * 16 + grp;
            #pragma unroll
            for (int nt = 0; nt < NT; nt++) {
                int c = wn + nt * 8 + tig * 2;
                int gate = c >> 5;
                int jj = c & 31;
                sg[(gate * 128 + r) * 33 + jj]         = acc[mt][nt][0];
                sg[(gate * 128 + r) * 33 + jj + 1]     = acc[mt][nt][1];
                sg[(gate * 128 + r + 8) * 33 + jj]     = acc[mt][nt][2];
                sg[(gate * 128 + r + 8) * 33 + jj + 1] = acc[mt][nt][3];
            }
        }
        __syncthreads();
        #pragma unroll
        for (int i = 0; i < 8; i++) {
            int idx = tid + i * 512;       // 128 rows x 32 cols
            int r = idx >> 5, j = idx & 31;
            int col = colBase + j;
            float gi = sg[r * 33 + j]            + bias[col];
            float gf = sg[(128 + r) * 33 + j]    + bias[HID + col];
            float gg = sg[(256 + r) * 33 + j]    + bias[2 * HID + col];
            float go = sg[(384 + r) * 33 + j]    + bias[3 * HID + col];
            size_t gx = (size_t)(rowBase + r) * HID + col;
            float cn = sigmoidf_(gf) * c_st[gx] + sigmoidf_(gi) * tanhf(gg);
            c_st[gx] = cn;
            h_new[gx] = sigmoidf_(go) * tanhf(cn);
        }
    } else {
        #pragma unroll
        for (int mt = 0; mt < MT; mt++) {
            int r = rowBase + wm + mt * 16 + grp;
            #pragma unroll
            for (int nt = 0; nt < NT; nt++) {
                int c = colBase + wn + nt * 8 + tig * 2;
                float b0v = bias[c];
                float b1v = bias[c + 1];
                *(float2*)&C[(size_t)r * N + c] =
                    make_float2(acc[mt][nt][0] + b0v, acc[mt][nt][1] + b1v);
                *(float2*)&C[(size_t)(r + 8) * N + c] =
                    make_float2(acc[mt][nt][2] + b0v, acc[mt][nt][3] + b1v);
            }
        }
    }
}

// ---------------------------------------------------------------------------
// 256-thread tf32 GEMM for p1 (BM=BN=64, warp tile 32x16, 8 warps).
// Same ring structure. Dynamic smem: 4*(64+64)*36*4 = 73728 B.
// ---------------------------------------------------------------------------
__global__ __launch_bounds__(256, 1)
void gemm_p1(const float* __restrict__ A1, const float* __restrict__ W1, int K1,
             const float* __restrict__ bias, float* __restrict__ C, int N)
{
    constexpr int BM = 64, BN = 64, WM = 32, WN = 16;
    constexpr int MT = WM / 16;        // 2
    constexpr int NT = WN / 8;         // 2
    constexpr int WGN = BN / WN;       // 4
    constexpr int BUFW = (BM + BN) * 36;

    extern __shared__ __align__(16) float sm[];

    const int tid  = threadIdx.x;
    const int lane = tid & 31;
    const int wid  = tid >> 5;
    const int wm   = (wid / WGN) * WM;
    const int wn   = (wid % WGN) * WN;
    const int grp  = lane >> 2;
    const int tig  = lane & 3;
    const int rowBase = blockIdx.y * BM;
    const int colBase = blockIdx.x * BN;

    const int tot = K1 >> 5;

    float acc[MT][NT][4];
    #pragma unroll
    for (int i = 0; i < MT; i++)
        #pragma unroll
        for (int j = 0; j < NT; j++)
            #pragma unroll
            for (int k = 0; k < 4; k++)
                acc[i][j][k] = 0.0f;

    auto issue = [&](int it, int b) {
        int k0 = it << 5;
        #pragma unroll
        for (int i = 0; i < BM / 32; i++) {
            int chunk = tid + i * 256;
            int r = chunk >> 3, c16 = chunk & 7;
            const float* g = A1 + (size_t)(rowBase + r) * K1 + k0 + c16 * 4;
            uint32_t s = (uint32_t)__cvta_generic_to_shared(&sm[b * BUFW + r * 36 + c16 * 4]);
            asm volatile("cp.async.cg.shared.global [%0], [%1], 16;\n" :: "r"(s), "l"(g));
        }
        #pragma unroll
        for (int i = 0; i < BN / 32; i++) {
            int chunk = tid + i * 256;
            int r = chunk >> 3, c16 = chunk & 7;
            const float* g = W1 + (size_t)(colBase + r) * K1 + k0 + c16 * 4;
            uint32_t s = (uint32_t)__cvta_generic_to_shared(&sm[b * BUFW + BM * 36 + r * 36 + c16 * 4]);
            asm volatile("cp.async.cg.shared.global [%0], [%1], 16;\n" :: "r"(s), "l"(g));
        }
    };

    auto compute = [&](int b) {
        const float* Asb = &sm[b * BUFW];
        const float* Wsb = &sm[b * BUFW + BM * 36];
        #pragma unroll
        for (int kk = 0; kk < 32; kk += 8) {
            uint32_t af[MT][4];
            #pragma unroll
            for (int mt = 0; mt < MT; mt++) {
                int r = wm + mt * 16 + grp;
                af[mt][0] = f2tf32(Asb[r * 36 + kk + tig]);
                af[mt][1] = f2tf32(Asb[(r + 8) * 36 + kk + tig]);
                af[mt][2] = f2tf32(Asb[r * 36 + kk + tig + 4]);
                af[mt][3] = f2tf32(Asb[(r + 8) * 36 + kk + tig + 4]);
            }
            uint32_t bf[NT][2];
            #pragma unroll
            for (int nt = 0; nt < NT; nt++) {
                int n = wn + nt * 8 + grp;
                bf[nt][0] = f2tf32(Wsb[n * 36 + kk + tig]);
                bf[nt][1] = f2tf32(Wsb[n * 36 + kk + tig + 4]);
            }
            #pragma unroll
            for (int mt = 0; mt < MT; mt++)
                #pragma unroll
                for (int nt = 0; nt < NT; nt++)
                    mma_tf32(acc[mt][nt], af[mt], bf[nt]);
        }
    };

    issue(0, 0);
    asm volatile("cp.async.commit_group;");
    if (tot > 1) {
        issue(1, 1);
        asm volatile("cp.async.commit_group;");
    }
    for (int it = 0; it < tot; it++) {
        if (it + 2 < tot) {
            issue(it + 2, (it + 2) & 3);
            asm volatile("cp.async.commit_group;");
        }
        int pend = tot - 1 - it;
        if (pend >= 2)      asm volatile("cp.async.wait_group 2;");
        else if (pend == 1) asm volatile("cp.async.wait_group 1;");
        else                asm volatile("cp.async.wait_group 0;");
        __syncthreads();
        compute(it & 3);
    }

    #pragma unroll
    for (int mt = 0; mt < MT; mt++) {
        int r = rowBase + wm + mt * 16 + grp;
        #pragma unroll
        for (int nt = 0; nt < NT; nt++) {
            int c = colBase + wn + nt * 8 + tig * 2;
            float b0v = bias[c];
            float b1v = bias[c + 1];
            *(float2*)&C[(size_t)r * N + c] =
                make_float2(acc[mt][nt][0] + b0v, acc[mt][nt][1] + b1v);
            *(float2*)&C[(size_t)(r + 8) * N + c] =
                make_float2(acc[mt][nt][2] + b0v, acc[mt][nt][3] + b1v);
        }
    }
}

// ---------------------------------------------------------------------------
// init: gelu(LN(z@lin1_w^T + lin1_b)) split into h0|c0, duplicated into both
// LSTM layers' state. One block per row, C = 2048.
// ---------------------------------------------------------------------------
__global__ void init_ln_gelu(const float* __restrict__ X,
                             const float* __restrict__ w,
                             const float* __restrict__ b,
                             float* __restrict__ h1, float* __restrict__ c1,
                             float* __restrict__ h2, float* __restrict__ c2)
{
    int row = blockIdx.x;
    const float* xr = X + (size_t)row * 2048;
    float v[8];
    float s = 0.0f, sq = 0.0f;
    #pragma unroll
    for (int i = 0; i < 8; i++) {
        v[i] = xr[threadIdx.x + i * 256];
        s += v[i];
        sq += v[i] * v[i];
    }
    block_reduce2(s, sq);
    float mu  = s * (1.0f / 2048.0f);
    float var = sq * (1.0f / 2048.0f) - mu * mu;
    float rs  = rsqrtf(var + EPS);
    #pragma unroll
    for (int i = 0; i < 8; i++) {
        int j = threadIdx.x + i * 256;
        float y = gelu_exact((v[i] - mu) * rs * w[j] + b[j]);
        if (j < HID) {
            h1[row * HID + j] = y;
            h2[row * HID + j] = y;
        } else {
            c1[row * HID + j - HID] = y;
            c2[row * HID + j - HID] = y;
        }
    }
}

// zero the step input
__global__ void zero_x() {
    int idx = blockIdx.x * blockDim.x + threadIdx.x;
    if (idx < BATCH * OUTD) g_x[idx] = 0.0f;
}

// ---------------------------------------------------------------------------
// Fused LN+GELU+p2: y = gelu(LN(p1)) @ p2_w^T  (512x128x1024)
// split-K=4, grid (8 mblk, 4 kslice), 256 threads, BM=64 BN=128 Kslice=256.
// ---------------------------------------------------------------------------
__global__ __launch_bounds__(256, 4)
void p2_fused(const float* __restrict__ p1,
              const float* __restrict__ pln_w, const float* __restrict__ pln_b,
              const float* __restrict__ w)
{
    __shared__ float As[32][68];    // [k][r]
    __shared__ float Wt[32][132];   // [k][n]
    __shared__ float smu[64], srs[64];
    __shared__ float spw[256], spb[256];

    int row0 = blockIdx.x * 64;
    int kbeg = blockIdx.y * 256;
    int tid = threadIdx.x;
    int wid = tid >> 5, lane = tid & 31;
    int tx = tid & 15;   // -> cols tx*8 .. +7
    int ty = tid >> 4;   // -> rows ty*4 .. +3

    spw[tid] = pln_w[kbeg + tid];
    spb[tid] = pln_b[kbeg + tid];

    // Phase 0: row stats (8 rows per warp, full 1024-wide scan each, fixed order)
    for (int rr = wid; rr < 64; rr += 8) {
        const float4* row = (const float4*)(p1 + (size_t)(row0 + rr) * HID);
        float s = 0.0f, sq = 0.0f;
        #pragma unroll
        for (int i = 0; i < 8; i++) {
            float4 v = row[lane + i * 32];
            s  += v.x + v.y + v.z + v.w;
            sq += v.x * v.x + v.y * v.y + v.z * v.z + v.w * v.w;
        }
        #pragma unroll
        for (int o = 16; o; o >>= 1) {
            s  += __shfl_xor_sync(0xffffffffu, s, o);
            sq += __shfl_xor_sync(0xffffffffu, sq, o);
        }
        if (lane == 0) {
            float mu  = s * (1.0f / 1024.0f);
            float var = sq * (1.0f / 1024.0f) - mu * mu;
            smu[rr] = mu;
            srs[rr] = rsqrtf(var + EPS);
        }
    }
    __syncthreads();

    float acc[4][8];
    #pragma unroll
    for (int i = 0; i < 4; i++)
        #pragma unroll
        for (int j = 0; j < 8; j++) acc[i][j] = 0.0f;

    for (int kc = 0; kc < 256; kc += 32) {
        __syncthreads();
        #pragma unroll
        for (int i = 0; i < 8; i++) {          // 2048 elems of A chunk
            int e = tid + i * 256;
            int k = e & 31, r = e >> 5;
            float v = p1[(size_t)(row0 + r) * HID + kbeg + kc + k];
            float ln = (v - smu[r]) * srs[r] * spw[kc + k] + spb[kc + k];
            As[k][r] = gelu_exact(ln);
        }
        #pragma unroll
        for (int i = 0; i < 16; i++) {         // 4096 elems of W chunk
            int e = tid + i * 256;
            int k = e & 31, n = e >> 5;
            Wt[k][n] = w[(size_t)n * HID + kbeg + kc + k];
        }
        __syncthreads();
        #pragma unroll
        for (int k = 0; k < 32; k++) {
            float4 a4 = *(const float4*)&As[k][ty * 4];
            float4 w0 = *(const float4*)&Wt[k][tx * 8];
            float4 w1 = *(const float4*)&Wt[k][tx * 8 + 4];
            float av[4] = {a4.x, a4.y, a4.z, a4.w};
            float wv[8] = {w0.x, w0.y, w0.z, w0.w, w1.x, w1.y, w1.z, w1.w};
            #pragma unroll
            for (int i = 0; i < 4; i++)
                #pragma unroll
                for (int j = 0; j < 8; j++)
                    acc[i][j] += av[i] * wv[j];
        }
    }
    float* dst = g_part + (size_t)blockIdx.y * (BATCH * OUTD);
    #pragma unroll
    for (int i = 0; i < 4; i++)
        #pragma unroll
        for (int j = 0; j < 8; j++)
            dst[(size_t)(row0 + ty * 4 + i) * OUTD + tx * 8 + j] = acc[i][j];
}

// fixed-order (deterministic) reduce; dual store: next-step x and out[:,t,:]
__global__ void p2_reduce(const float* __restrict__ bias, float* __restrict__ out, int t)
{
    int idx = blockIdx.x * 256 + threadIdx.x;  // < 512*128
    int bb = idx >> 7, n = idx & 127;
    float s = bias[n];
    #pragma unroll
    for (int p = 0; p < 4; p++) s += g_part[p * (BATCH * OUTD) + idx];
    g_x[idx] = s;                                   // next step's input
    out[(size_t)bb * (SEQ * OUTD) + t * OUTD + n] = s;  // (BATCH, SEQ, OUT)
}

// ---------------------------------------------------------------------------
// Launcher: ~483 graph nodes, all default stream, no sync, no alloc,
// no static guards.
// ---------------------------------------------------------------------------
extern "C" void kernel_launch(void* const* d_in, const int* in_sizes, int n_in,
                              void* d_out, int out_size)
{
    const float* z      = (const float*)d_in[0];
    const float* lin1_w = (const float*)d_in[1];
    const float* lin1_b = (const float*)d_in[2];
    const float* ln1_w  = (const float*)d_in[3];
    const float* ln1_b  = (const float*)d_in[4];
    const float* w_ih0  = (const float*)d_in[5];
    const float* w_hh0  = (const float*)d_in[6];
    const float* b0     = (const float*)d_in[7];
    const float* w_ih1  = (const float*)d_in[8];
    const float* w_hh1  = (const float*)d_in[9];
    const float* b1     = (const float*)d_in[10];
    const float* p1_w   = (const float*)d_in[11];
    const float* p1_b   = (const float*)d_in[12];
    const float* pln_w  = (const float*)d_in[13];
    const float* pln_b  = (const float*)d_in[14];
    const float* p2_w   = (const float*)d_in[15];
    const float* p2_b   = (const float*)d_in[16];
    float* out = (float*)d_out;

    float *tmp, *h1a, *h1b, *c1, *h2a, *h2b, *c2, *x, *p1o;
    cudaGetSymbolAddress((void**)&tmp, g_tmp);
    cudaGetSymbolAddress((void**)&h1a, g_h1a);
    cudaGetSymbolAddress((void**)&h1b, g_h1b);
    cudaGetSymbolAddress((void**)&c1, g_c1);
    cudaGetSymbolAddress((void**)&h2a, g_h2a);
    cudaGetSymbolAddress((void**)&h2b, g_h2b);
    cudaGetSymbolAddress((void**)&c2, g_c2);
    cudaGetSymbolAddress((void**)&x, g_x);
    cudaGetSymbolAddress((void**)&p1o, g_p1);

    constexpr int SMEM_G = 4 * 256 * 36 * 4;           // 147456 B (gemm512)
    constexpr int SMEM_P = 4 * (64 + 64) * 36 * 4;     //  73728 B (gemm_p1)
    // idempotent, capture-safe, NO static guard (harness forbids them)
    cudaFuncSetAttribute(gemm512<false>,
                         cudaFuncAttributeMaxDynamicSharedMemorySize, SMEM_G);
    cudaFuncSetAttribute(gemm512<true>,
                         cudaFuncAttributeMaxDynamicSharedMemorySize, SMEM_G);
    cudaFuncSetAttribute(gemm_p1,
                         cudaFuncAttributeMaxDynamicSharedMemorySize, SMEM_P);

    // x0 = 0
    zero_x<<<(BATCH * OUTD + 255) / 256, 256>>>();

    // init: tmp = z @ lin1_w^T + lin1_b  (512 x 2048), then LN+gelu -> states
    gemm512<false><<<dim3(2048 / 128, BATCH / 128), 512, SMEM_G>>>(
        z, lin1_w, LATENT, nullptr, nullptr, 0, lin1_b,
        tmp, 2048, nullptr, nullptr);
    init_ln_gelu<<<BATCH, 256>>>(tmp, ln1_w, ln1_b, h1a, c1, h2a, c2);

    float *h1o = h1a, *h1n = h1b, *h2o = h2a, *h2n = h2b;
    for (int t = 0; t < SEQ; t++) {
        // layer-1 LSTM: gates = x @ w_ih0^T + h1o @ w_hh0^T + b0, fused cell
        gemm512<true><<<dim3(HID / 32, BATCH / 128), 512, SMEM_G>>>(
            x, w_ih0, OUTD, h1o, w_hh0, HID, b0,
            nullptr, 0, c1, h1n);

        // layer-2 LSTM: gates = h1n @ w_ih1^T + h2o @ w_hh1^T + b1, fused cell
        gemm512<true><<<dim3(HID / 32, BATCH / 128), 512, SMEM_G>>>(
            h1n, w_ih1, HID, h2o, w_hh1, HID, b1,
            nullptr, 0, c2, h2n);

        // p1 = h2n @ p1_w^T + p1_b (pre-LN)
        gemm_p1<<<dim3(HID / 64, BATCH / 64), 256, SMEM_P>>>(
            h2n, p1_w, HID, p1_b, p1o, HID);

        // y = gelu(LN(p1)) @ p2_w^T + p2_b -> g_x AND out[:, t, :]
        p2_fused<<<dim3(8, 4), 256>>>(p1o, pln_w, pln_b, p2_w);
        p2_reduce<<<(BATCH * OUTD) / 256, 256>>>(p2_b, out, t);

        // ping-pong h buffers
        float* tp;
        tp = h1o; h1o = h1n; h1n = tp;
        tp = h2o; h2o = h2n; h2n = tp;
    }
    (void)in_sizes; (void)n_in; (void)out_size;
}

// round 10
// speedup vs baseline: 1.5722x; 1.5722x over previous
#include <cuda_runtime.h>
#include <cstdint>

#define BATCH  512
#define LATENT 256
#define HID    1024
#define OUTD   128
#define SEQ    96
#define GATES  4096   // 4*HID
#define EPS    1e-5f

// ---------------------------------------------------------------------------
// Persistent device scratch (static __device__ arrays — no runtime alloc).
// ---------------------------------------------------------------------------
__device__ float g_tmp[BATCH * 2048];       // init-GEMM tmp (512x2048)
__device__ float g_h1a[BATCH * HID];
__device__ float g_h1b[BATCH * HID];
__device__ float g_c1[BATCH * HID];
__device__ float g_h2a[BATCH * HID];
__device__ float g_h2b[BATCH * HID];
__device__ float g_c2[BATCH * HID];
__device__ float g_x[BATCH * OUTD];         // step input (y of previous step)
__device__ float g_p1[BATCH * HID];         // p1 GEMM output (pre-LN)
__device__ float g_part[4 * BATCH * OUTD];  // p2 split-K partials

// ---------------------------------------------------------------------------
// Helpers
// ---------------------------------------------------------------------------
__device__ __forceinline__ uint32_t f2tf32(float f) {
    uint32_t r;
    asm("cvt.rna.tf32.f32 %0, %1;" : "=r"(r) : "f"(f));
    return r;
}

__device__ __forceinline__ void mma_tf32(float* d, const uint32_t* a, const uint32_t* b) {
    asm volatile(
        "mma.sync.aligned.m16n8k8.row.col.f32.tf32.tf32.f32 "
        "{%0,%1,%2,%3}, {%4,%5,%6,%7}, {%8,%9}, {%0,%1,%2,%3};"
        : "+f"(d[0]), "+f"(d[1]), "+f"(d[2]), "+f"(d[3])
        : "r"(a[0]), "r"(a[1]), "r"(a[2]), "r"(a[3]),
          "r"(b[0]), "r"(b[1]));
}

__device__ __forceinline__ float gelu_exact(float x) {
    return 0.5f * x * (1.0f + erff(x * 0.70710678118654752f));
}
__device__ __forceinline__ float sigmoidf_(float x) {
    return 1.0f / (1.0f + expf(-x));
}

// block-wide sum of two values (blockDim.x == 256)
__device__ __forceinline__ void block_reduce2(float& a, float& b) {
    __shared__ float sa[8], sb[8];
    #pragma unroll
    for (int o = 16; o; o >>= 1) {
        a += __shfl_xor_sync(0xffffffffu, a, o);
        b += __shfl_xor_sync(0xffffffffu, b, o);
    }
    int w = threadIdx.x >> 5, l = threadIdx.x & 31;
    if (l == 0) { sa[w] = a; sb[w] = b; }
    __syncthreads();
    if (threadIdx.x < 32) {
        float ta = (l < 8) ? sa[l] : 0.0f;
        float tb = (l < 8) ? sb[l] : 0.0f;
        #pragma unroll
        for (int o = 4; o; o >>= 1) {
            ta += __shfl_xor_sync(0xffffffffu, ta, o);
            tb += __shfl_xor_sync(0xffffffffu, tb, o);
        }
        if (l == 0) { sa[0] = ta; sb[0] = tb; }
    }
    __syncthreads();
    a = sa[0];
    b = sb[0];
}

// ---------------------------------------------------------------------------
// 512-thread tf32 GEMM: 16 warps = 8 output warp-tiles (64x32) x 2 K-slices.
// Each warp computes HALF the kk-range of its tile (ks = wid>>3); partial
// sums merged once through smem at the end. This keeps R6's efficient
// 1.5 LDS/MMA instruction mix while doubling warps/SMSP (2 -> 4).
//   result = A1[M,K1] @ W1^T (+ A2[M,K2] @ W2^T) + bias
// LSTM mode: block bx covers columns j0=bx*32 of ALL FOUR gates
// (W rows {j, HID+j, 2HID+j, 3HID+j}); epilogue computes c/h in-kernel.
// 4-stage cp.async ring, issue distance 2, ONE __syncthreads per K-iter.
// Dynamic smem: 4*256*36*4 = 147456 B.
// ---------------------------------------------------------------------------
template<bool LSTM>
__global__ __launch_bounds__(512, 1)
void gemm512(const float* __restrict__ A1, const float* __restrict__ W1, int K1,
             const float* __restrict__ A2, const float* __restrict__ W2, int K2,
             const float* __restrict__ bias,
             float* __restrict__ C, int N,
             float* __restrict__ c_st, float* __restrict__ h_new)
{
    constexpr int MT = 4;              // 64 rows = 4 x m16
    constexpr int NT = 4;              // 32 cols = 4 x n8
    constexpr int BUFW = 256 * 36;     // floats per ring buffer (A 128 + W 128 rows)

    extern __shared__ __align__(16) float sm[];

    const int tid  = threadIdx.x;
    const int lane = tid & 31;
    const int wid  = tid >> 5;            // 0..15
    const int ks   = wid >> 3;            // K-slice: 0 or 1
    const int w8   = wid & 7;             // output-tile id 0..7
    const int wm   = (w8 >> 2) * 64;      // warp row offset (2 row-groups)
    const int wn   = (w8 & 3) * 32;       // warp col offset (4 col-groups)
    const int grp  = lane >> 2;
    const int tig  = lane & 3;
    const int rowBase = blockIdx.y * 128;
    const int colBase = blockIdx.x * (LSTM ? 32 : 128);  // j0 in LSTM mode

    const int n1 = K1 >> 5;
    const int n2 = K2 >> 5;
    const int tot = n1 + n2;

    float acc[MT][NT][4];
    #pragma unroll
    for (int i = 0; i < MT; i++)
        #pragma unroll
        for (int j = 0; j < NT; j++)
            #pragma unroll
            for (int k = 0; k < 4; k++)
                acc[i][j][k] = 0.0f;

    auto issue = [&](int it, int b) {
        const float* A; const float* W; int K; int k0;
        if (it < n1) { A = A1; W = W1; K = K1; k0 = it << 5; }
        else         { A = A2; W = W2; K = K2; k0 = (it - n1) << 5; }
        // A tile: 128 rows x 8 float4 chunks = 1024 chunks, 2 per thread
        #pragma unroll
        for (int i = 0; i < 2; i++) {
            int chunk = tid + i * 512;
            int r = chunk >> 3, c16 = chunk & 7;
            const float* g = A + (size_t)(rowBase + r) * K + k0 + c16 * 4;
            uint32_t s = (uint32_t)__cvta_generic_to_shared(&sm[b * BUFW + r * 36 + c16 * 4]);
            asm volatile("cp.async.cg.shared.global [%0], [%1], 16;\n" :: "r"(s), "l"(g));
        }
        // W tile: 128 rows x 8 chunks
        #pragma unroll
        for (int i = 0; i < 2; i++) {
            int chunk = tid + i * 512;
            int r = chunk >> 3, c16 = chunk & 7;
            int wrow = LSTM ? ((r >> 5) * HID + colBase + (r & 31)) : (colBase + r);
            const float* g = W + (size_t)wrow * K + k0 + c16 * 4;
            uint32_t s = (uint32_t)__cvta_generic_to_shared(&sm[b * BUFW + 128 * 36 + r * 36 + c16 * 4]);
            asm volatile("cp.async.cg.shared.global [%0], [%1], 16;\n" :: "r"(s), "l"(g));
        }
    };

    auto compute = [&](int b) {
        const float* Asb = &sm[b * BUFW];
        const float* Wsb = &sm[b * BUFW + 128 * 36];
        #pragma unroll
        for (int kh = 0; kh < 2; kh++) {
            int kk = ks * 16 + kh * 8;     // this warp's K-slice half
            uint32_t af[MT][4];
            #pragma unroll
            for (int mt = 0; mt < MT; mt++) {
                int r = wm + mt * 16 + grp;
                af[mt][0] = f2tf32(Asb[r * 36 + kk + tig]);
                af[mt][1] = f2tf32(Asb[(r + 8) * 36 + kk + tig]);
                af[mt][2] = f2tf32(Asb[r * 36 + kk + tig + 4]);
                af[mt][3] = f2tf32(Asb[(r + 8) * 36 + kk + tig + 4]);
            }
            uint32_t bf[NT][2];
            #pragma unroll
            for (int nt = 0; nt < NT; nt++) {
                int n = wn + nt * 8 + grp;
                bf[nt][0] = f2tf32(Wsb[n * 36 + kk + tig]);
                bf[nt][1] = f2tf32(Wsb[n * 36 + kk + tig + 4]);
            }
            #pragma unroll
            for (int mt = 0; mt < MT; mt++)
                #pragma unroll
                for (int nt = 0; nt < NT; nt++)
                    mma_tf32(acc[mt][nt], af[mt], bf[nt]);
        }
    };

    // 4-stage ring, issue distance 2: prologue issues groups 0,1.
    issue(0, 0);
    asm volatile("cp.async.commit_group;");
    if (tot > 1) {
        issue(1, 1);
        asm volatile("cp.async.commit_group;");
    }
    for (int it = 0; it < tot; it++) {
        if (it + 2 < tot) {
            issue(it + 2, (it + 2) & 3);   // buffer last consumed by compute(it-2)
            asm volatile("cp.async.commit_group;");
        }
        int pend = tot - 1 - it;           // committed groups newer than 'it'
        if (pend >= 2)      asm volatile("cp.async.wait_group 2;");
        else if (pend == 1) asm volatile("cp.async.wait_group 1;");
        else                asm volatile("cp.async.wait_group 0;");
        __syncthreads();                   // single barrier per K-iteration
        compute(it & 3);
    }

    // ---- merge the two K-slices: ks=1 publishes, ks=0 accumulates ----
    float* red = sm;                       // 128 x 132 staging (67.6 KB)
    __syncthreads();                       // ring buffers fully consumed
    if (ks == 1) {
        #pragma unroll
        for (int mt = 0; mt < MT; mt++) {
            int r = wm + mt * 16 + grp;
            #pragma unroll
            for (int nt = 0; nt < NT; nt++) {
                int c = wn + nt * 8 + tig * 2;
                *(float2*)&red[r * 132 + c]       = make_float2(acc[mt][nt][0], acc[mt][nt][1]);
                *(float2*)&red[(r + 8) * 132 + c] = make_float2(acc[mt][nt][2], acc[mt][nt][3]);
            }
        }
    }
    __syncthreads();
    if (ks == 0) {
        #pragma unroll
        for (int mt = 0; mt < MT; mt++) {
            int r = wm + mt * 16 + grp;
            #pragma unroll
            for (int nt = 0; nt < NT; nt++) {
                int c = wn + nt * 8 + tig * 2;
                float2 v0 = *(float2*)&red[r * 132 + c];
                float2 v1 = *(float2*)&red[(r + 8) * 132 + c];
                acc[mt][nt][0] += v0.x;  acc[mt][nt][1] += v0.y;
                acc[mt][nt][2] += v1.x;  acc[mt][nt][3] += v1.y;
            }
        }
    }

    if constexpr (LSTM) {
        __syncthreads();   // red reads done before sg overwrites same smem
        // ks=0 warps stage the four 128x32 gate tiles (stride 33, 67.6 KB).
        float* sg = sm;
        if (ks == 0) {
            #pragma unroll
            for (int mt = 0; mt < MT; mt++) {
                int r = wm + mt * 16 + grp;
                #pragma unroll
                for (int nt = 0; nt < NT; nt++) {
                    int c = wn + nt * 8 + tig * 2;
                    int gate = c >> 5;
                    int jj = c & 31;
                    sg[(gate * 128 + r) * 33 + jj]         = acc[mt][nt][0];
                    sg[(gate * 128 + r) * 33 + jj + 1]     = acc[mt][nt][1];
                    sg[(gate * 128 + r + 8) * 33 + jj]     = acc[mt][nt][2];
                    sg[(gate * 128 + r + 8) * 33 + jj + 1] = acc[mt][nt][3];
                }
            }
        }
        __syncthreads();
        #pragma unroll
        for (int i = 0; i < 8; i++) {
            int idx = tid + i * 512;       // 128 rows x 32 cols
            int r = idx >> 5, j = idx & 31;
            int col = colBase + j;
            float gi = sg[r * 33 + j]            + bias[col];
            float gf = sg[(128 + r) * 33 + j]    + bias[HID + col];
            float gg = sg[(256 + r) * 33 + j]    + bias[2 * HID + col];
            float go = sg[(384 + r) * 33 + j]    + bias[3 * HID + col];
            size_t gx = (size_t)(rowBase + r) * HID + col;
            float cn = sigmoidf_(gf) * c_st[gx] + sigmoidf_(gi) * tanhf(gg);
            c_st[gx] = cn;
            h_new[gx] = sigmoidf_(go) * tanhf(cn);
        }
    } else {
        if (ks == 0) {
            #pragma unroll
            for (int mt = 0; mt < MT; mt++) {
                int r = rowBase + wm + mt * 16 + grp;
                #pragma unroll
                for (int nt = 0; nt < NT; nt++) {
                    int c = colBase + wn + nt * 8 + tig * 2;
                    float b0v = bias[c];
                    float b1v = bias[c + 1];
                    *(float2*)&C[(size_t)r * N + c] =
                        make_float2(acc[mt][nt][0] + b0v, acc[mt][nt][1] + b1v);
                    *(float2*)&C[(size_t)(r + 8) * N + c] =
                        make_float2(acc[mt][nt][2] + b0v, acc[mt][nt][3] + b1v);
                }
            }
        }
    }
}

// ---------------------------------------------------------------------------
// 256-thread tf32 GEMM for p1 (BM=BN=64, warp tile 32x16, 8 warps).
// Same ring structure. Dynamic smem: 4*(64+64)*36*4 = 73728 B.
// ---------------------------------------------------------------------------
__global__ __launch_bounds__(256, 1)
void gemm_p1(const float* __restrict__ A1, const float* __restrict__ W1, int K1,
             const float* __restrict__ bias, float* __restrict__ C, int N)
{
    constexpr int BM = 64, BN = 64, WM = 32, WN = 16;
    constexpr int MT = WM / 16;        // 2
    constexpr int NT = WN / 8;         // 2
    constexpr int WGN = BN / WN;       // 4
    constexpr int BUFW = (BM + BN) * 36;

    extern __shared__ __align__(16) float sm[];

    const int tid  = threadIdx.x;
    const int lane = tid & 31;
    const int wid  = tid >> 5;
    const int wm   = (wid / WGN) * WM;
    const int wn   = (wid % WGN) * WN;
    const int grp  = lane >> 2;
    const int tig  = lane & 3;
    const int rowBase = blockIdx.y * BM;
    const int colBase = blockIdx.x * BN;

    const int tot = K1 >> 5;

    float acc[MT][NT][4];
    #pragma unroll
    for (int i = 0; i < MT; i++)
        #pragma unroll
        for (int j = 0; j < NT; j++)
            #pragma unroll
            for (int k = 0; k < 4; k++)
                acc[i][j][k] = 0.0f;

    auto issue = [&](int it, int b) {
        int k0 = it << 5;
        #pragma unroll
        for (int i = 0; i < BM / 32; i++) {
            int chunk = tid + i * 256;
            int r = chunk >> 3, c16 = chunk & 7;
            const float* g = A1 + (size_t)(rowBase + r) * K1 + k0 + c16 * 4;
            uint32_t s = (uint32_t)__cvta_generic_to_shared(&sm[b * BUFW + r * 36 + c16 * 4]);
            asm volatile("cp.async.cg.shared.global [%0], [%1], 16;\n" :: "r"(s), "l"(g));
        }
        #pragma unroll
        for (int i = 0; i < BN / 32; i++) {
            int chunk = tid + i * 256;
            int r = chunk >> 3, c16 = chunk & 7;
            const float* g = W1 + (size_t)(colBase + r) * K1 + k0 + c16 * 4;
            uint32_t s = (uint32_t)__cvta_generic_to_shared(&sm[b * BUFW + BM * 36 + r * 36 + c16 * 4]);
            asm volatile("cp.async.cg.shared.global [%0], [%1], 16;\n" :: "r"(s), "l"(g));
        }
    };

    auto compute = [&](int b) {
        const float* Asb = &sm[b * BUFW];
        const float* Wsb = &sm[b * BUFW + BM * 36];
        #pragma unroll
        for (int kk = 0; kk < 32; kk += 8) {
            uint32_t af[MT][4];
            #pragma unroll
            for (int mt = 0; mt < MT; mt++) {
                int r = wm + mt * 16 + grp;
                af[mt][0] = f2tf32(Asb[r * 36 + kk + tig]);
                af[mt][1] = f2tf32(Asb[(r + 8) * 36 + kk + tig]);
                af[mt][2] = f2tf32(Asb[r * 36 + kk + tig + 4]);
                af[mt][3] = f2tf32(Asb[(r + 8) * 36 + kk + tig + 4]);
            }
            uint32_t bf[NT][2];
            #pragma unroll
            for (int nt = 0; nt < NT; nt++) {
                int n = wn + nt * 8 + grp;
                bf[nt][0] = f2tf32(Wsb[n * 36 + kk + tig]);
                bf[nt][1] = f2tf32(Wsb[n * 36 + kk + tig + 4]);
            }
            #pragma unroll
            for (int mt = 0; mt < MT; mt++)
                #pragma unroll
                for (int nt = 0; nt < NT; nt++)
                    mma_tf32(acc[mt][nt], af[mt], bf[nt]);
        }
    };

    issue(0, 0);
    asm volatile("cp.async.commit_group;");
    if (tot > 1) {
        issue(1, 1);
        asm volatile("cp.async.commit_group;");
    }
    for (int it = 0; it < tot; it++) {
        if (it + 2 < tot) {
            issue(it + 2, (it + 2) & 3);
            asm volatile("cp.async.commit_group;");
        }
        int pend = tot - 1 - it;
        if (pend >= 2)      asm volatile("cp.async.wait_group 2;");
        else if (pend == 1) asm volatile("cp.async.wait_group 1;");
        else                asm volatile("cp.async.wait_group 0;");
        __syncthreads();
        compute(it & 3);
    }

    #pragma unroll
    for (int mt = 0; mt < MT; mt++) {
        int r = rowBase + wm + mt * 16 + grp;
        #pragma unroll
        for (int nt = 0; nt < NT; nt++) {
            int c = colBase + wn + nt * 8 + tig * 2;
            float b0v = bias[c];
            float b1v = bias[c + 1];
            *(float2*)&C[(size_t)r * N + c] =
                make_float2(acc[mt][nt][0] + b0v, acc[mt][nt][1] + b1v);
            *(float2*)&C[(size_t)(r + 8) * N + c] =
                make_float2(acc[mt][nt][2] + b0v, acc[mt][nt][3] + b1v);
        }
    }
}

// ---------------------------------------------------------------------------
// init: gelu(LN(z@lin1_w^T + lin1_b)) split into h0|c0, duplicated into both
// LSTM layers' state. One block per row, C = 2048.
// ---------------------------------------------------------------------------
__global__ void init_ln_gelu(const float* __restrict__ X,
                             const float* __restrict__ w,
                             const float* __restrict__ b,
                             float* __restrict__ h1, float* __restrict__ c1,
                             float* __restrict__ h2, float* __restrict__ c2)
{
    int row = blockIdx.x;
    const float* xr = X + (size_t)row * 2048;
    float v[8];
    float s = 0.0f, sq = 0.0f;
    #pragma unroll
    for (int i = 0; i < 8; i++) {
        v[i] = xr[threadIdx.x + i * 256];
        s += v[i];
        sq += v[i] * v[i];
    }
    block_reduce2(s, sq);
    float mu  = s * (1.0f / 2048.0f);
    float var = sq * (1.0f / 2048.0f) - mu * mu;
    float rs  = rsqrtf(var + EPS);
    #pragma unroll
    for (int i = 0; i < 8; i++) {
        int j = threadIdx.x + i * 256;
        float y = gelu_exact((v[i] - mu) * rs * w[j] + b[j]);
        if (j < HID) {
            h1[row * HID + j] = y;
            h2[row * HID + j] = y;
        } else {
            c1[row * HID + j - HID] = y;
            c2[row * HID + j - HID] = y;
        }
    }
}

// zero the step input
__global__ void zero_x() {
    int idx = blockIdx.x * blockDim.x + threadIdx.x;
    if (idx < BATCH * OUTD) g_x[idx] = 0.0f;
}

// ---------------------------------------------------------------------------
// Fused LN+GELU+p2: y = gelu(LN(p1)) @ p2_w^T  (512x128x1024)
// split-K=4, grid (8 mblk, 4 kslice), 256 threads, BM=64 BN=128 Kslice=256.
// ---------------------------------------------------------------------------
__global__ __launch_bounds__(256, 4)
void p2_fused(const float* __restrict__ p1,
              const float* __restrict__ pln_w, const float* __restrict__ pln_b,
              const float* __restrict__ w)
{
    __shared__ float As[32][68];    // [k][r]
    __shared__ float Wt[32][132];   // [k][n]
    __shared__ float smu[64], srs[64];
    __shared__ float spw[256], spb[256];

    int row0 = blockIdx.x * 64;
    int kbeg = blockIdx.y * 256;
    int tid = threadIdx.x;
    int wid = tid >> 5, lane = tid & 31;
    int tx = tid & 15;   // -> cols tx*8 .. +7
    int ty = tid >> 4;   // -> rows ty*4 .. +3

    spw[tid] = pln_w[kbeg + tid];
    spb[tid] = pln_b[kbeg + tid];

    // Phase 0: row stats (8 rows per warp, full 1024-wide scan each, fixed order)
    for (int rr = wid; rr < 64; rr += 8) {
        const float4* row = (const float4*)(p1 + (size_t)(row0 + rr) * HID);
        float s = 0.0f, sq = 0.0f;
        #pragma unroll
        for (int i = 0; i < 8; i++) {
            float4 v = row[lane + i * 32];
            s  += v.x + v.y + v.z + v.w;
            sq += v.x * v.x + v.y * v.y + v.z * v.z + v.w * v.w;
        }
        #pragma unroll
        for (int o = 16; o; o >>= 1) {
            s  += __shfl_xor_sync(0xffffffffu, s, o);
            sq += __shfl_xor_sync(0xffffffffu, sq, o);
        }
        if (lane == 0) {
            float mu  = s * (1.0f / 1024.0f);
            float var = sq * (1.0f / 1024.0f) - mu * mu;
            smu[rr] = mu;
            srs[rr] = rsqrtf(var + EPS);
        }
    }
    __syncthreads();

    float acc[4][8];
    #pragma unroll
    for (int i = 0; i < 4; i++)
        #pragma unroll
        for (int j = 0; j < 8; j++) acc[i][j] = 0.0f;

    for (int kc = 0; kc < 256; kc += 32) {
        __syncthreads();
        #pragma unroll
        for (int i = 0; i < 8; i++) {          // 2048 elems of A chunk
            int e = tid + i * 256;
            int k = e & 31, r = e >> 5;
            float v = p1[(size_t)(row0 + r) * HID + kbeg + kc + k];
            float ln = (v - smu[r]) * srs[r] * spw[kc + k] + spb[kc + k];
            As[k][r] = gelu_exact(ln);
        }
        #pragma unroll
        for (int i = 0; i < 16; i++) {         // 4096 elems of W chunk
            int e = tid + i * 256;
            int k = e & 31, n = e >> 5;
            Wt[k][n] = w[(size_t)n * HID + kbeg + kc + k];
        }
        __syncthreads();
        #pragma unroll
        for (int k = 0; k < 32; k++) {
            float4 a4 = *(const float4*)&As[k][ty * 4];
            float4 w0 = *(const float4*)&Wt[k][tx * 8];
            float4 w1 = *(const float4*)&Wt[k][tx * 8 + 4];
            float av[4] = {a4.x, a4.y, a4.z, a4.w};
            float wv[8] = {w0.x, w0.y, w0.z, w0.w, w1.x, w1.y, w1.z, w1.w};
            #pragma unroll
            for (int i = 0; i < 4; i++)
                #pragma unroll
                for (int j = 0; j < 8; j++)
                    acc[i][j] += av[i] * wv[j];
        }
    }
    float* dst = g_part + (size_t)blockIdx.y * (BATCH * OUTD);
    #pragma unroll
    for (int i = 0; i < 4; i++)
        #pragma unroll
        for (int j = 0; j < 8; j++)
            dst[(size_t)(row0 + ty * 4 + i) * OUTD + tx * 8 + j] = acc[i][j];
}

// fixed-order (deterministic) reduce; dual store: next-step x and out[:,t,:]
__global__ void p2_reduce(const float* __restrict__ bias, float* __restrict__ out, int t)
{
    int idx = blockIdx.x * 256 + threadIdx.x;  // < 512*128
    int bb = idx >> 7, n = idx & 127;
    float s = bias[n];
    #pragma unroll
    for (int p = 0; p < 4; p++) s += g_part[p * (BATCH * OUTD) + idx];
    g_x[idx] = s;                                   // next step's input
    out[(size_t)bb * (SEQ * OUTD) + t * OUTD + n] = s;  // (BATCH, SEQ, OUT)
}

// ---------------------------------------------------------------------------
// Launcher: ~483 graph nodes, all default stream, no sync, no alloc,
// no static guards.
// ---------------------------------------------------------------------------
extern "C" void kernel_launch(void* const* d_in, const int* in_sizes, int n_in,
                              void* d_out, int out_size)
{
    const float* z      = (const float*)d_in[0];
    const float* lin1_w = (const float*)d_in[1];
    const float* lin1_b = (const float*)d_in[2];
    const float* ln1_w  = (const float*)d_in[3];
    const float* ln1_b  = (const float*)d_in[4];
    const float* w_ih0  = (const float*)d_in[5];
    const float* w_hh0  = (const float*)d_in[6];
    const float* b0     = (const float*)d_in[7];
    const float* w_ih1  = (const float*)d_in[8];
    const float* w_hh1  = (const float*)d_in[9];
    const float* b1     = (const float*)d_in[10];
    const float* p1_w   = (const float*)d_in[11];
    const float* p1_b   = (const float*)d_in[12];
    const float* pln_w  = (const float*)d_in[13];
    const float* pln_b  = (const float*)d_in[14];
    const float* p2_w   = (const float*)d_in[15];
    const float* p2_b   = (const float*)d_in[16];
    float* out = (float*)d_out;

    float *tmp, *h1a, *h1b, *c1, *h2a, *h2b, *c2, *x, *p1o;
    cudaGetSymbolAddress((void**)&tmp, g_tmp);
    cudaGetSymbolAddress((void**)&h1a, g_h1a);
    cudaGetSymbolAddress((void**)&h1b, g_h1b);
    cudaGetSymbolAddress((void**)&c1, g_c1);
    cudaGetSymbolAddress((void**)&h2a, g_h2a);
    cudaGetSymbolAddress((void**)&h2b, g_h2b);
    cudaGetSymbolAddress((void**)&c2, g_c2);
    cudaGetSymbolAddress((void**)&x, g_x);
    cudaGetSymbolAddress((void**)&p1o, g_p1);

    constexpr int SMEM_G = 4 * 256 * 36 * 4;           // 147456 B (gemm512)
    constexpr int SMEM_P = 4 * (64 + 64) * 36 * 4;     //  73728 B (gemm_p1)
    // idempotent, capture-safe, NO static guard (harness forbids them)
    cudaFuncSetAttribute(gemm512<false>,
                         cudaFuncAttributeMaxDynamicSharedMemorySize, SMEM_G);
    cudaFuncSetAttribute(gemm512<true>,
                         cudaFuncAttributeMaxDynamicSharedMemorySize, SMEM_G);
    cudaFuncSetAttribute(gemm_p1,
                         cudaFuncAttributeMaxDynamicSharedMemorySize, SMEM_P);

    // x0 = 0
    zero_x<<<(BATCH * OUTD + 255) / 256, 256>>>();

    // init: tmp = z @ lin1_w^T + lin1_b  (512 x 2048), then LN+gelu -> states
    gemm512<false><<<dim3(2048 / 128, BATCH / 128), 512, SMEM_G>>>(
        z, lin1_w, LATENT, nullptr, nullptr, 0, lin1_b,
        tmp, 2048, nullptr, nullptr);
    init_ln_gelu<<<BATCH, 256>>>(tmp, ln1_w, ln1_b, h1a, c1, h2a, c2);

    float *h1o = h1a, *h1n = h1b, *h2o = h2a, *h2n = h2b;
    for (int t = 0; t < SEQ; t++) {
        // layer-1 LSTM: gates = x @ w_ih0^T + h1o @ w_hh0^T + b0, fused cell
        gemm512<true><<<dim3(HID / 32, BATCH / 128), 512, SMEM_G>>>(
            x, w_ih0, OUTD, h1o, w_hh0, HID, b0,
            nullptr, 0, c1, h1n);

        // layer-2 LSTM: gates = h1n @ w_ih1^T + h2o @ w_hh1^T + b1, fused cell
        gemm512<true><<<dim3(HID / 32, BATCH / 128), 512, SMEM_G>>>(
            h1n, w_ih1, HID, h2o, w_hh1, HID, b1,
            nullptr, 0, c2, h2n);

        // p1 = h2n @ p1_w^T + p1_b (pre-LN)
        gemm_p1<<<dim3(HID / 64, BATCH / 64), 256, SMEM_P>>>(
            h2n, p1_w, HID, p1_b, p1o, HID);

        // y = gelu(LN(p1)) @ p2_w^T + p2_b -> g_x AND out[:, t, :]
        p2_fused<<<dim3(8, 4), 256>>>(p1o, pln_w, pln_b, p2_w);
        p2_reduce<<<(BATCH * OUTD) / 256, 256>>>(p2_b, out, t);

        // ping-pong h buffers
        float* tp;
        tp = h1o; h1o = h1n; h1n = tp;
        tp = h2o; h2o = h2n; h2n = tp;
    }
    (void)in_sizes; (void)n_in; (void)out_size;
}